// round 4
// baseline (speedup 1.0000x reference)
#include <cuda_runtime.h>
#include <math.h>
#include <stdint.h>

#define NN 50000
#define EE 800000
#define IN_DIM 128
#define EMB 64
#define HDIM 256
#define RR 12
#define BB 8
#define NHEADS 4
#define NGENE 20000
#define NPATH 2000
#define IN1 192
#define NR (NN * RR)

// ---------------- static scratch ----------------
__device__ float g_x0[(size_t)NN * IN1];
__device__ float g_h1[(size_t)NN * HDIM];
__device__ float g_h2[(size_t)NN * HDIM];
__device__ float g_aggB[(size_t)NN * BB * HDIM];
__device__ int   g_cnt[NR];
__device__ int   g_off[NR];
__device__ int   g_wof[NR];
__device__ int   g_esrc[EE];

// ---------------- helpers ----------------
__device__ __forceinline__ uint32_t smem_u32(const void* p) {
    uint32_t a;
    asm("{ .reg .u64 t; cvta.to.shared.u64 t, %1; cvt.u32.u64 %0, t; }" : "=r"(a) : "l"(p));
    return a;
}
__device__ __forceinline__ uint32_t f2tf32(float f) {
    uint32_t r; asm("cvt.rna.tf32.f32 %0, %1;" : "=r"(r) : "f"(f)); return r;
}
__device__ __forceinline__ void split_tf32(float f, uint32_t& hi, uint32_t& lo) {
    hi = f2tf32(f);
    lo = f2tf32(f - __uint_as_float(hi));
}
__device__ __forceinline__ void mma8(float* d, const uint32_t* a, const uint32_t* b) {
    asm volatile(
        "mma.sync.aligned.m16n8k8.row.col.f32.tf32.tf32.f32 "
        "{%0,%1,%2,%3}, {%4,%5,%6,%7}, {%8,%9}, {%0,%1,%2,%3};"
        : "+f"(d[0]), "+f"(d[1]), "+f"(d[2]), "+f"(d[3])
        : "r"(a[0]), "r"(a[1]), "r"(a[2]), "r"(a[3]), "r"(b[0]), "r"(b[1]));
}
__device__ __forceinline__ void cp16(uint32_t dst, const float* src) {
    asm volatile("cp.async.cg.shared.global [%0], [%1], 16;" :: "r"(dst), "l"(src));
}

// ---------------- 1: build x0 + zero counts ----------------
__global__ void k_build(const float* __restrict__ x) {
    int i = blockIdx.x * blockDim.x + threadIdx.x;
    if (i < NR) g_cnt[i] = 0;
    if (i >= NN * IN1) return;
    int n = i / IN1, c = i - n * IN1;
    g_x0[i] = (c < IN_DIM) ? x[(size_t)n * IN_DIM + c] : 0.0f;
}

// ---------------- 2: per-(node,rel) edge counts ----------------
__global__ void k_count(const int* __restrict__ ei, const int* __restrict__ et) {
    int e = blockIdx.x * blockDim.x + threadIdx.x;
    if (e >= EE) return;
    atomicAdd(&g_cnt[ei[EE + e] * RR + et[e]], 1);
}

// ---------------- 3: single-block exclusive scan over 600K counts ----------------
__global__ void k_scan() {
    __shared__ int bs[1024];
    const int CH = (NR + 1023) / 1024;   // 586
    int t = threadIdx.x;
    int base = t * CH;
    int s = 0;
    for (int j = 0; j < CH; j++) {
        int i = base + j;
        if (i < NR) s += g_cnt[i];
    }
    bs[t] = s;
    __syncthreads();
    for (int off = 1; off < 1024; off <<= 1) {
        int v = (t >= off) ? bs[t - off] : 0;
        __syncthreads();
        bs[t] += v;
        __syncthreads();
    }
    int run = (t == 0) ? 0 : bs[t - 1];
    for (int j = 0; j < CH; j++) {
        int i = base + j;
        if (i < NR) {
            g_off[i] = run;
            g_wof[i] = run;
            run += g_cnt[i];
        }
    }
}

// ---------------- 4: CSR fill + embedding adds (fused) ----------------
#define FILL_TOT (EE + (NGENE + NPATH) * EMB)
__global__ void k_fill_embs(const int* __restrict__ ei, const int* __restrict__ et,
                            const int* __restrict__ gidx, const int* __restrict__ pidx,
                            const float* __restrict__ gemb, const float* __restrict__ pemb) {
    int i = blockIdx.x * blockDim.x + threadIdx.x;
    if (i < EE) {
        int flat = ei[EE + i] * RR + et[i];
        int p = atomicAdd(&g_wof[flat], 1);
        g_esrc[p] = ei[i];
    } else if (i < EE + NGENE * EMB) {
        int t = i - EE;
        int g = t / EMB, j = t - g * EMB;
        g_x0[(size_t)gidx[g] * IN1 + IN_DIM + j] += gemb[t];
    } else if (i < FILL_TOT) {
        int t = i - EE - NGENE * EMB;
        int g = t / EMB, j = t - g * EMB;
        g_x0[(size_t)pidx[g] * IN1 + IN_DIM + j] += pemb[t];
    }
}

// ---------------- 5/7: gather-aggregate directly into aggB ----------------
// one block per node, blockDim = K. accB[b] in registers.
template <int K, int LAYER>
__global__ void __launch_bounds__(K)
k_agg(const float* __restrict__ comp) {
    __shared__ float sc[RR * BB];
    const int tid = threadIdx.x;
    const int n = blockIdx.x;
    if (tid < RR * BB) sc[tid] = comp[tid];
    __syncthreads();

    const float* __restrict__ xin = (LAYER == 1) ? g_x0 : g_h1;

    float accB[BB];
#pragma unroll
    for (int b = 0; b < BB; b++) accB[b] = 0.f;

#pragma unroll
    for (int r = 0; r < RR; r++) {
        int flat = n * RR + r;
        int c = g_cnt[flat];
        if (c == 0) continue;
        int off = g_off[flat];
        float s = 0.f;
        for (int j = 0; j < c; j++) {
            int src = __ldg(&g_esrc[off + j]);
            s += xin[(size_t)src * K + tid];
        }
        float sm = s / (float)c;
#pragma unroll
        for (int b = 0; b < BB; b++)
            accB[b] = fmaf(sc[r * BB + b], sm, accB[b]);
    }

    float* dst = g_aggB + (size_t)n * (BB * K) + tid;
#pragma unroll
    for (int b = 0; b < BB; b++) dst[b * K] = accB[b];
}

// ---------------- tensor-core GEMM via mma.sync (3xTF32) + bias + head-softmax ----------------
#define GEMM_SMEM_FLOATS 15104
#define GEMM_SMEM_BYTES  (GEMM_SMEM_FLOATS * 4)

template <int KIN, int LAYER>
__global__ void __launch_bounds__(256, 1)
k_gemm_mma(const float* __restrict__ basis, const float* __restrict__ root,
           const float* __restrict__ bias,  const float* __restrict__ att) {
    constexpr int KB   = BB * KIN;
    constexpr int KTOT = 9 * KIN;
    constexpr int T    = KTOT / 16;

    extern __shared__ float sm[];
    float* As     = sm;            // [2][128][20]
    float* Bs     = sm + 5120;     // [2][16][264]
    float* s_bias = sm + 13568;
    float* s_att  = sm + 13824;
    float* s_sc   = sm + 14080;    // [128][4]
    float* s_al   = sm + 14592;    // [128][4]

    const uint32_t smbase = smem_u32(sm);
    const int tid  = threadIdx.x;
    const int lane = tid & 31;
    const int wid  = tid >> 5;
    const int wm   = wid >> 2;
    const int wn   = wid & 3;
    const int m0   = blockIdx.x * 128;

    const float* xin  = (LAYER == 1) ? g_x0 : g_h1;
    float*       hout = (LAYER == 1) ? g_h1 : g_h2;

    s_bias[tid] = bias[tid];
    s_att[tid]  = att[tid];

    float acc[4][8][4];
#pragma unroll
    for (int a = 0; a < 4; a++)
#pragma unroll
        for (int b = 0; b < 8; b++)
#pragma unroll
            for (int c = 0; c < 4; c++) acc[a][b][c] = 0.f;

    auto issueA = [&](int t) {
#pragma unroll
        for (int i = 0; i < 2; ++i) {
            int id = tid + i * 256;
            int m = id >> 2, k4 = (id & 3) << 2;
            int row = m0 + m;
            int kc = t * 16 + k4;
            uint32_t dst = smbase + (((t & 1) * 2560 + m * 20 + k4) << 2);
            if (row < NN) {
                const float* src = (kc < KB) ? (g_aggB + (size_t)row * KB + kc)
                                             : (xin + (size_t)row * KIN + (kc - KB));
                cp16(dst, src);
            } else {
                asm volatile("st.shared.v4.b32 [%0], {%1,%1,%1,%1};" :: "r"(dst), "r"(0) : "memory");
            }
        }
    };
    auto issueB = [&](int t) {
#pragma unroll
        for (int i = 0; i < 4; ++i) {
            int id = tid + i * 256;
            int k = id >> 6, n4 = (id & 63) << 2;
            int kk = t * 16 + k;
            const float* src = (kk < KB) ? (basis + (size_t)kk * 256 + n4)
                                         : (root + (size_t)(kk - KB) * 256 + n4);
            uint32_t dst = smbase + ((5120 + (t & 1) * 4224 + k * 264 + n4) << 2);
            cp16(dst, src);
        }
    };

    issueA(0); issueB(0);
    asm volatile("cp.async.commit_group;" ::: "memory");

    for (int t = 0; t < T; ++t) {
        asm volatile("cp.async.wait_group 0;" ::: "memory");
        __syncthreads();
        if (t + 1 < T) {
            issueA(t + 1); issueB(t + 1);
            asm volatile("cp.async.commit_group;" ::: "memory");
        }
        const float* Ac = As + (t & 1) * 2560;
        const float* Bc = Bs + (t & 1) * 4224;
#pragma unroll
        for (int kk0 = 0; kk0 < 16; kk0 += 8) {
            uint32_t ah[4][4], al_[4][4];
#pragma unroll
            for (int mi = 0; mi < 4; ++mi) {
                int mr = wm * 64 + mi * 16 + (lane >> 2);
                int kc0 = kk0 + (lane & 3);
                float f0 = Ac[mr * 20 + kc0];
                float f1 = Ac[(mr + 8) * 20 + kc0];
                float f2 = Ac[mr * 20 + kc0 + 4];
                float f3 = Ac[(mr + 8) * 20 + kc0 + 4];
                split_tf32(f0, ah[mi][0], al_[mi][0]);
                split_tf32(f1, ah[mi][1], al_[mi][1]);
                split_tf32(f2, ah[mi][2], al_[mi][2]);
                split_tf32(f3, ah[mi][3], al_[mi][3]);
            }
#pragma unroll
            for (int ni = 0; ni < 8; ++ni) {
                int nc = wn * 64 + ni * 8 + (lane >> 2);
                float g0 = Bc[(kk0 + (lane & 3)) * 264 + nc];
                float g1 = Bc[(kk0 + (lane & 3) + 4) * 264 + nc];
                uint32_t bh[2], bl[2];
                split_tf32(g0, bh[0], bl[0]);
                split_tf32(g1, bh[1], bl[1]);
#pragma unroll
                for (int mi = 0; mi < 4; ++mi) {
                    mma8(acc[mi][ni], ah[mi], bh);
                    mma8(acc[mi][ni], ah[mi], bl);
                    mma8(acc[mi][ni], al_[mi], bh);
                }
            }
        }
    }

    // ---- bias + head scores ----
    float sc[8];
#pragma unroll
    for (int i = 0; i < 8; ++i) sc[i] = 0.f;
#pragma unroll
    for (int mi = 0; mi < 4; ++mi)
#pragma unroll
        for (int ni = 0; ni < 8; ++ni) {
            int colb = wn * 64 + ni * 8 + (lane & 3) * 2;
#pragma unroll
            for (int r = 0; r < 4; ++r) {
                int col = colb + (r & 1);
                acc[mi][ni][r] += s_bias[col];
                sc[mi * 2 + (r >> 1)] = fmaf(acc[mi][ni][r], s_att[col], sc[mi * 2 + (r >> 1)]);
            }
        }
#pragma unroll
    for (int i = 0; i < 8; ++i) {
        sc[i] += __shfl_xor_sync(0xffffffffu, sc[i], 1);
        sc[i] += __shfl_xor_sync(0xffffffffu, sc[i], 2);
    }
    if ((lane & 3) == 0) {
#pragma unroll
        for (int mi = 0; mi < 4; ++mi) {
            int r0 = wm * 64 + mi * 16 + (lane >> 2);
            s_sc[r0 * 4 + wn]       = sc[mi * 2];
            s_sc[(r0 + 8) * 4 + wn] = sc[mi * 2 + 1];
        }
    }
    __syncthreads();
    if (tid < 128) {
        float v0 = s_sc[tid * 4], v1 = s_sc[tid * 4 + 1];
        float v2 = s_sc[tid * 4 + 2], v3 = s_sc[tid * 4 + 3];
        float mx = fmaxf(fmaxf(v0, v1), fmaxf(v2, v3));
        float e0 = expf(v0 - mx), e1 = expf(v1 - mx), e2 = expf(v2 - mx), e3 = expf(v3 - mx);
        float inv = 1.f / (e0 + e1 + e2 + e3);
        s_al[tid * 4]     = e0 * inv;
        s_al[tid * 4 + 1] = e1 * inv;
        s_al[tid * 4 + 2] = e2 * inv;
        s_al[tid * 4 + 3] = e3 * inv;
    }
    __syncthreads();

    // ---- scaled store ----
#pragma unroll
    for (int mi = 0; mi < 4; ++mi) {
        int lr0 = wm * 64 + mi * 16 + (lane >> 2);
        int rowA = m0 + lr0, rowB = rowA + 8;
        float aA = s_al[lr0 * 4 + wn];
        float aB = s_al[(lr0 + 8) * 4 + wn];
#pragma unroll
        for (int ni = 0; ni < 8; ++ni) {
            int col = wn * 64 + ni * 8 + (lane & 3) * 2;
            if (rowA < NN) {
                float2 o = make_float2(acc[mi][ni][0] * aA, acc[mi][ni][1] * aA);
                *reinterpret_cast<float2*>(&hout[(size_t)rowA * HDIM + col]) = o;
            }
            if (rowB < NN) {
                float2 o = make_float2(acc[mi][ni][2] * aB, acc[mi][ni][3] * aB);
                *reinterpret_cast<float2*>(&hout[(size_t)rowB * HDIM + col]) = o;
            }
        }
    }
}

// ---------------- 9: final prediction ----------------
__global__ void k_pred(const float* __restrict__ pw, const float* __restrict__ pb,
                       float* __restrict__ out) {
    __shared__ float wt[12 * HDIM];
    int tid = threadIdx.x;
    for (int i = tid; i < HDIM * 12; i += blockDim.x) {
        int c = i / 12, j = i - c * 12;
        wt[j * HDIM + c] = pw[i];
    }
    __syncthreads();
    int warp = tid >> 5, lane = tid & 31;
    int n = blockIdx.x * 8 + warp;
    if (n >= NN) return;
    float acc[12];
#pragma unroll
    for (int j = 0; j < 12; j++) acc[j] = 0.f;
#pragma unroll
    for (int c0 = 0; c0 < 8; c0++) {
        int c = c0 * 32 + lane;
        float v = g_h2[(size_t)n * HDIM + c];
#pragma unroll
        for (int j = 0; j < 12; j++) acc[j] = fmaf(v, wt[j * HDIM + c], acc[j]);
    }
#pragma unroll
    for (int j = 0; j < 12; j++) {
#pragma unroll
        for (int off = 16; off; off >>= 1)
            acc[j] += __shfl_xor_sync(0xffffffffu, acc[j], off);
    }
    if (lane == 0) {
#pragma unroll
        for (int j = 0; j < 12; j++) out[(size_t)n * 12 + j] = acc[j] + pb[j];
    }
}

// ---------------- launch ----------------
extern "C" void kernel_launch(void* const* d_in, const int* in_sizes, int n_in,
                              void* d_out, int out_size) {
    const float* x      = (const float*)d_in[0];
    const int*   ei     = (const int*)d_in[1];
    const int*   et     = (const int*)d_in[2];
    const int*   gidx   = (const int*)d_in[3];
    const int*   pidx   = (const int*)d_in[4];
    const float* gemb   = (const float*)d_in[5];
    const float* pemb   = (const float*)d_in[6];
    const float* comp1  = (const float*)d_in[7];
    const float* basis1 = (const float*)d_in[8];
    const float* root1  = (const float*)d_in[9];
    const float* bias1  = (const float*)d_in[10];
    const float* att1   = (const float*)d_in[11];
    const float* comp2  = (const float*)d_in[12];
    const float* basis2 = (const float*)d_in[13];
    const float* root2  = (const float*)d_in[14];
    const float* bias2  = (const float*)d_in[15];
    const float* att2   = (const float*)d_in[16];
    const float* predw  = (const float*)d_in[17];
    const float* predb  = (const float*)d_in[18];
    float* out = (float*)d_out;

    const int TPB = 256;

    cudaFuncSetAttribute(k_gemm_mma<IN1, 1>,  cudaFuncAttributeMaxDynamicSharedMemorySize, GEMM_SMEM_BYTES);
    cudaFuncSetAttribute(k_gemm_mma<HDIM, 2>, cudaFuncAttributeMaxDynamicSharedMemorySize, GEMM_SMEM_BYTES);

    // 1: x0 + zero counts
    k_build<<<(NN * IN1 + TPB - 1) / TPB, TPB>>>(x);
    // 2: counts
    k_count<<<(EE + TPB - 1) / TPB, TPB>>>(ei, et);
    // 3: scan -> offsets
    k_scan<<<1, 1024>>>();
    // 4: CSR fill + embeddings (profiled slot)
    k_fill_embs<<<(FILL_TOT + TPB - 1) / TPB, TPB>>>(ei, et, gidx, pidx, gemb, pemb);
    // 5: aggregate layer 1
    k_agg<IN1, 1><<<NN, IN1>>>(comp1);
    // 6: GEMM layer 1
    k_gemm_mma<IN1, 1><<<(NN + 127) / 128, 256, GEMM_SMEM_BYTES>>>(basis1, root1, bias1, att1);
    // 7: aggregate layer 2
    k_agg<HDIM, 2><<<NN, HDIM>>>(comp2);
    // 8: GEMM layer 2
    k_gemm_mma<HDIM, 2><<<(NN + 127) / 128, 256, GEMM_SMEM_BYTES>>>(basis2, root2, bias2, att2);
    // 9: prediction head
    k_pred<<<(NN + 7) / 8, TPB>>>(predw, predb, out);
}

// round 5
// speedup vs baseline: 1.0021x; 1.0021x over previous
#include <cuda_runtime.h>
#include <math.h>
#include <stdint.h>

#define NN 50000
#define EE 800000
#define IN_DIM 128
#define EMB 64
#define HDIM 256
#define RR 12
#define BB 8
#define NHEADS 4
#define NGENE 20000
#define NPATH 2000
#define IN1 192
#define NR (NN * RR)

// ---------------- static scratch ----------------
__device__ float g_x0[(size_t)NN * IN1];
__device__ float g_h1[(size_t)NN * HDIM];
__device__ float g_h2[(size_t)NN * HDIM];
__device__ float g_aggB[(size_t)NN * BB * HDIM];
__device__ int   g_cnt[NR];
__device__ int   g_off[NR];
__device__ int   g_wof[NR];
__device__ int   g_esrc[EE];

// ---------------- helpers ----------------
__device__ __forceinline__ uint32_t smem_u32(const void* p) {
    uint32_t a;
    asm("{ .reg .u64 t; cvta.to.shared.u64 t, %1; cvt.u32.u64 %0, t; }" : "=r"(a) : "l"(p));
    return a;
}
__device__ __forceinline__ uint32_t f2tf32(float f) {
    uint32_t r; asm("cvt.rna.tf32.f32 %0, %1;" : "=r"(r) : "f"(f)); return r;
}
__device__ __forceinline__ void split_tf32(float f, uint32_t& hi, uint32_t& lo) {
    hi = f2tf32(f);
    lo = f2tf32(f - __uint_as_float(hi));
}
__device__ __forceinline__ void mma8(float* d, const uint32_t* a, const uint32_t* b) {
    asm volatile(
        "mma.sync.aligned.m16n8k8.row.col.f32.tf32.tf32.f32 "
        "{%0,%1,%2,%3}, {%4,%5,%6,%7}, {%8,%9}, {%0,%1,%2,%3};"
        : "+f"(d[0]), "+f"(d[1]), "+f"(d[2]), "+f"(d[3])
        : "r"(a[0]), "r"(a[1]), "r"(a[2]), "r"(a[3]), "r"(b[0]), "r"(b[1]));
}
__device__ __forceinline__ void cp16(uint32_t dst, const float* src) {
    asm volatile("cp.async.cg.shared.global [%0], [%1], 16;" :: "r"(dst), "l"(src));
}

// ---------------- 1: build x0 + zero counts ----------------
__global__ void k_build(const float* __restrict__ x) {
    int i = blockIdx.x * blockDim.x + threadIdx.x;
    if (i < NR) g_cnt[i] = 0;
    if (i >= NN * IN1) return;
    int n = i / IN1, c = i - n * IN1;
    g_x0[i] = (c < IN_DIM) ? x[(size_t)n * IN_DIM + c] : 0.0f;
}

// ---------------- 2: per-(node,rel) edge counts ----------------
__global__ void k_count(const int* __restrict__ ei, const int* __restrict__ et) {
    int e = blockIdx.x * blockDim.x + threadIdx.x;
    if (e >= EE) return;
    atomicAdd(&g_cnt[ei[EE + e] * RR + et[e]], 1);
}

// ---------------- 3: single-block exclusive scan over 600K counts ----------------
__global__ void k_scan() {
    __shared__ int bs[1024];
    const int CH = (NR + 1023) / 1024;   // 586
    int t = threadIdx.x;
    int base = t * CH;
    int s = 0;
    for (int j = 0; j < CH; j++) {
        int i = base + j;
        if (i < NR) s += g_cnt[i];
    }
    bs[t] = s;
    __syncthreads();
    for (int off = 1; off < 1024; off <<= 1) {
        int v = (t >= off) ? bs[t - off] : 0;
        __syncthreads();
        bs[t] += v;
        __syncthreads();
    }
    int run = (t == 0) ? 0 : bs[t - 1];
    for (int j = 0; j < CH; j++) {
        int i = base + j;
        if (i < NR) {
            g_off[i] = run;
            g_wof[i] = run;
            run += g_cnt[i];
        }
    }
}

// ---------------- 4: CSR fill + embedding adds (fused) ----------------
#define FILL_TOT (EE + (NGENE + NPATH) * EMB)
__global__ void k_fill_embs(const int* __restrict__ ei, const int* __restrict__ et,
                            const int* __restrict__ gidx, const int* __restrict__ pidx,
                            const float* __restrict__ gemb, const float* __restrict__ pemb) {
    int i = blockIdx.x * blockDim.x + threadIdx.x;
    if (i < EE) {
        int flat = ei[EE + i] * RR + et[i];
        int p = atomicAdd(&g_wof[flat], 1);
        g_esrc[p] = ei[i];
    } else if (i < EE + NGENE * EMB) {
        int t = i - EE;
        int g = t / EMB, j = t - g * EMB;
        g_x0[(size_t)gidx[g] * IN1 + IN_DIM + j] += gemb[t];
    } else if (i < FILL_TOT) {
        int t = i - EE - NGENE * EMB;
        int g = t / EMB, j = t - g * EMB;
        g_x0[(size_t)pidx[g] * IN1 + IN_DIM + j] += pemb[t];
    }
}

// ---------------- 5/7: gather-aggregate directly into aggB ----------------
// one block per node, blockDim = K. accB[b] in registers.
template <int K, int LAYER>
__global__ void __launch_bounds__(K)
k_agg(const float* __restrict__ comp) {
    __shared__ float sc[RR * BB];
    const int tid = threadIdx.x;
    const int n = blockIdx.x;
    if (tid < RR * BB) sc[tid] = comp[tid];
    __syncthreads();

    const float* __restrict__ xin = (LAYER == 1) ? g_x0 : g_h1;

    float accB[BB];
#pragma unroll
    for (int b = 0; b < BB; b++) accB[b] = 0.f;

#pragma unroll
    for (int r = 0; r < RR; r++) {
        int flat = n * RR + r;
        int c = g_cnt[flat];
        if (c == 0) continue;
        int off = g_off[flat];
        float s = 0.f;
        for (int j = 0; j < c; j++) {
            int src = __ldg(&g_esrc[off + j]);
            s += xin[(size_t)src * K + tid];
        }
        float sm = s / (float)c;
#pragma unroll
        for (int b = 0; b < BB; b++)
            accB[b] = fmaf(sc[r * BB + b], sm, accB[b]);
    }

    float* dst = g_aggB + (size_t)n * (BB * K) + tid;
#pragma unroll
    for (int b = 0; b < BB; b++) dst[b * K] = accB[b];
}

// ---------------- tensor-core GEMM via mma.sync (3xTF32) + bias + head-softmax ----------------
#define GEMM_SMEM_FLOATS 15104
#define GEMM_SMEM_BYTES  (GEMM_SMEM_FLOATS * 4)

template <int KIN, int LAYER>
__global__ void __launch_bounds__(256, 1)
k_gemm_mma(const float* __restrict__ basis, const float* __restrict__ root,
           const float* __restrict__ bias,  const float* __restrict__ att) {
    constexpr int KB   = BB * KIN;
    constexpr int KTOT = 9 * KIN;
    constexpr int T    = KTOT / 16;

    extern __shared__ float sm[];
    float* As     = sm;            // [2][128][20]
    float* Bs     = sm + 5120;     // [2][16][264]
    float* s_bias = sm + 13568;
    float* s_att  = sm + 13824;
    float* s_sc   = sm + 14080;    // [128][4]
    float* s_al   = sm + 14592;    // [128][4]

    const uint32_t smbase = smem_u32(sm);
    const int tid  = threadIdx.x;
    const int lane = tid & 31;
    const int wid  = tid >> 5;
    const int wm   = wid >> 2;
    const int wn   = wid & 3;
    const int m0   = blockIdx.x * 128;

    const float* xin  = (LAYER == 1) ? g_x0 : g_h1;
    float*       hout = (LAYER == 1) ? g_h1 : g_h2;

    s_bias[tid] = bias[tid];
    s_att[tid]  = att[tid];

    float acc[4][8][4];
#pragma unroll
    for (int a = 0; a < 4; a++)
#pragma unroll
        for (int b = 0; b < 8; b++)
#pragma unroll
            for (int c = 0; c < 4; c++) acc[a][b][c] = 0.f;

    auto issueA = [&](int t) {
#pragma unroll
        for (int i = 0; i < 2; ++i) {
            int id = tid + i * 256;
            int m = id >> 2, k4 = (id & 3) << 2;
            int row = m0 + m;
            int kc = t * 16 + k4;
            uint32_t dst = smbase + (((t & 1) * 2560 + m * 20 + k4) << 2);
            if (row < NN) {
                const float* src = (kc < KB) ? (g_aggB + (size_t)row * KB + kc)
                                             : (xin + (size_t)row * KIN + (kc - KB));
                cp16(dst, src);
            } else {
                asm volatile("st.shared.v4.b32 [%0], {%1,%1,%1,%1};" :: "r"(dst), "r"(0) : "memory");
            }
        }
    };
    auto issueB = [&](int t) {
#pragma unroll
        for (int i = 0; i < 4; ++i) {
            int id = tid + i * 256;
            int k = id >> 6, n4 = (id & 63) << 2;
            int kk = t * 16 + k;
            const float* src = (kk < KB) ? (basis + (size_t)kk * 256 + n4)
                                         : (root + (size_t)(kk - KB) * 256 + n4);
            uint32_t dst = smbase + ((5120 + (t & 1) * 4224 + k * 264 + n4) << 2);
            cp16(dst, src);
        }
    };

    issueA(0); issueB(0);
    asm volatile("cp.async.commit_group;" ::: "memory");

    for (int t = 0; t < T; ++t) {
        asm volatile("cp.async.wait_group 0;" ::: "memory");
        __syncthreads();
        if (t + 1 < T) {
            issueA(t + 1); issueB(t + 1);
            asm volatile("cp.async.commit_group;" ::: "memory");
        }
        const float* Ac = As + (t & 1) * 2560;
        const float* Bc = Bs + (t & 1) * 4224;
#pragma unroll
        for (int kk0 = 0; kk0 < 16; kk0 += 8) {
            uint32_t ah[4][4], al_[4][4];
#pragma unroll
            for (int mi = 0; mi < 4; ++mi) {
                int mr = wm * 64 + mi * 16 + (lane >> 2);
                int kc0 = kk0 + (lane & 3);
                float f0 = Ac[mr * 20 + kc0];
                float f1 = Ac[(mr + 8) * 20 + kc0];
                float f2 = Ac[mr * 20 + kc0 + 4];
                float f3 = Ac[(mr + 8) * 20 + kc0 + 4];
                split_tf32(f0, ah[mi][0], al_[mi][0]);
                split_tf32(f1, ah[mi][1], al_[mi][1]);
                split_tf32(f2, ah[mi][2], al_[mi][2]);
                split_tf32(f3, ah[mi][3], al_[mi][3]);
            }
#pragma unroll
            for (int ni = 0; ni < 8; ++ni) {
                int nc = wn * 64 + ni * 8 + (lane >> 2);
                float g0 = Bc[(kk0 + (lane & 3)) * 264 + nc];
                float g1 = Bc[(kk0 + (lane & 3) + 4) * 264 + nc];
                uint32_t bh[2], bl[2];
                split_tf32(g0, bh[0], bl[0]);
                split_tf32(g1, bh[1], bl[1]);
#pragma unroll
                for (int mi = 0; mi < 4; ++mi) {
                    mma8(acc[mi][ni], ah[mi], bh);
                    mma8(acc[mi][ni], ah[mi], bl);
                    mma8(acc[mi][ni], al_[mi], bh);
                }
            }
        }
    }

    // ---- bias + head scores ----
    float sc[8];
#pragma unroll
    for (int i = 0; i < 8; ++i) sc[i] = 0.f;
#pragma unroll
    for (int mi = 0; mi < 4; ++mi)
#pragma unroll
        for (int ni = 0; ni < 8; ++ni) {
            int colb = wn * 64 + ni * 8 + (lane & 3) * 2;
#pragma unroll
            for (int r = 0; r < 4; ++r) {
                int col = colb + (r & 1);
                acc[mi][ni][r] += s_bias[col];
                sc[mi * 2 + (r >> 1)] = fmaf(acc[mi][ni][r], s_att[col], sc[mi * 2 + (r >> 1)]);
            }
        }
#pragma unroll
    for (int i = 0; i < 8; ++i) {
        sc[i] += __shfl_xor_sync(0xffffffffu, sc[i], 1);
        sc[i] += __shfl_xor_sync(0xffffffffu, sc[i], 2);
    }
    if ((lane & 3) == 0) {
#pragma unroll
        for (int mi = 0; mi < 4; ++mi) {
            int r0 = wm * 64 + mi * 16 + (lane >> 2);
            s_sc[r0 * 4 + wn]       = sc[mi * 2];
            s_sc[(r0 + 8) * 4 + wn] = sc[mi * 2 + 1];
        }
    }
    __syncthreads();
    if (tid < 128) {
        float v0 = s_sc[tid * 4], v1 = s_sc[tid * 4 + 1];
        float v2 = s_sc[tid * 4 + 2], v3 = s_sc[tid * 4 + 3];
        float mx = fmaxf(fmaxf(v0, v1), fmaxf(v2, v3));
        float e0 = expf(v0 - mx), e1 = expf(v1 - mx), e2 = expf(v2 - mx), e3 = expf(v3 - mx);
        float inv = 1.f / (e0 + e1 + e2 + e3);
        s_al[tid * 4]     = e0 * inv;
        s_al[tid * 4 + 1] = e1 * inv;
        s_al[tid * 4 + 2] = e2 * inv;
        s_al[tid * 4 + 3] = e3 * inv;
    }
    __syncthreads();

    // ---- scaled store ----
#pragma unroll
    for (int mi = 0; mi < 4; ++mi) {
        int lr0 = wm * 64 + mi * 16 + (lane >> 2);
        int rowA = m0 + lr0, rowB = rowA + 8;
        float aA = s_al[lr0 * 4 + wn];
        float aB = s_al[(lr0 + 8) * 4 + wn];
#pragma unroll
        for (int ni = 0; ni < 8; ++ni) {
            int col = wn * 64 + ni * 8 + (lane & 3) * 2;
            if (rowA < NN) {
                float2 o = make_float2(acc[mi][ni][0] * aA, acc[mi][ni][1] * aA);
                *reinterpret_cast<float2*>(&hout[(size_t)rowA * HDIM + col]) = o;
            }
            if (rowB < NN) {
                float2 o = make_float2(acc[mi][ni][2] * aB, acc[mi][ni][3] * aB);
                *reinterpret_cast<float2*>(&hout[(size_t)rowB * HDIM + col]) = o;
            }
        }
    }
}

// ---------------- 9: final prediction ----------------
__global__ void k_pred(const float* __restrict__ pw, const float* __restrict__ pb,
                       float* __restrict__ out) {
    __shared__ float wt[12 * HDIM];
    int tid = threadIdx.x;
    for (int i = tid; i < HDIM * 12; i += blockDim.x) {
        int c = i / 12, j = i - c * 12;
        wt[j * HDIM + c] = pw[i];
    }
    __syncthreads();
    int warp = tid >> 5, lane = tid & 31;
    int n = blockIdx.x * 8 + warp;
    if (n >= NN) return;
    float acc[12];
#pragma unroll
    for (int j = 0; j < 12; j++) acc[j] = 0.f;
#pragma unroll
    for (int c0 = 0; c0 < 8; c0++) {
        int c = c0 * 32 + lane;
        float v = g_h2[(size_t)n * HDIM + c];
#pragma unroll
        for (int j = 0; j < 12; j++) acc[j] = fmaf(v, wt[j * HDIM + c], acc[j]);
    }
#pragma unroll
    for (int j = 0; j < 12; j++) {
#pragma unroll
        for (int off = 16; off; off >>= 1)
            acc[j] += __shfl_xor_sync(0xffffffffu, acc[j], off);
    }
    if (lane == 0) {
#pragma unroll
        for (int j = 0; j < 12; j++) out[(size_t)n * 12 + j] = acc[j] + pb[j];
    }
}

// ---------------- launch ----------------
extern "C" void kernel_launch(void* const* d_in, const int* in_sizes, int n_in,
                              void* d_out, int out_size) {
    const float* x      = (const float*)d_in[0];
    const int*   ei     = (const int*)d_in[1];
    const int*   et     = (const int*)d_in[2];
    const int*   gidx   = (const int*)d_in[3];
    const int*   pidx   = (const int*)d_in[4];
    const float* gemb   = (const float*)d_in[5];
    const float* pemb   = (const float*)d_in[6];
    const float* comp1  = (const float*)d_in[7];
    const float* basis1 = (const float*)d_in[8];
    const float* root1  = (const float*)d_in[9];
    const float* bias1  = (const float*)d_in[10];
    const float* att1   = (const float*)d_in[11];
    const float* comp2  = (const float*)d_in[12];
    const float* basis2 = (const float*)d_in[13];
    const float* root2  = (const float*)d_in[14];
    const float* bias2  = (const float*)d_in[15];
    const float* att2   = (const float*)d_in[16];
    const float* predw  = (const float*)d_in[17];
    const float* predb  = (const float*)d_in[18];
    float* out = (float*)d_out;

    const int TPB = 256;

    cudaFuncSetAttribute(k_gemm_mma<IN1, 1>,  cudaFuncAttributeMaxDynamicSharedMemorySize, GEMM_SMEM_BYTES);
    cudaFuncSetAttribute(k_gemm_mma<HDIM, 2>, cudaFuncAttributeMaxDynamicSharedMemorySize, GEMM_SMEM_BYTES);

    // 1: x0 + zero counts
    k_build<<<(NN * IN1 + TPB - 1) / TPB, TPB>>>(x);
    // 2: counts
    k_count<<<(EE + TPB - 1) / TPB, TPB>>>(ei, et);
    // 3: scan -> offsets
    k_scan<<<1, 1024>>>();
    // 4: CSR fill + embeddings (profiled slot)
    k_fill_embs<<<(FILL_TOT + TPB - 1) / TPB, TPB>>>(ei, et, gidx, pidx, gemb, pemb);
    // 5: aggregate layer 1
    k_agg<IN1, 1><<<NN, IN1>>>(comp1);
    // 6: GEMM layer 1
    k_gemm_mma<IN1, 1><<<(NN + 127) / 128, 256, GEMM_SMEM_BYTES>>>(basis1, root1, bias1, att1);
    // 7: aggregate layer 2
    k_agg<HDIM, 2><<<NN, HDIM>>>(comp2);
    // 8: GEMM layer 2
    k_gemm_mma<HDIM, 2><<<(NN + 127) / 128, 256, GEMM_SMEM_BYTES>>>(basis2, root2, bias2, att2);
    // 9: prediction head
    k_pred<<<(NN + 7) / 8, TPB>>>(predw, predb, out);
}

// round 6
// speedup vs baseline: 1.2519x; 1.2493x over previous
#include <cuda_runtime.h>
#include <math.h>
#include <stdint.h>

#define NN 50000
#define EE 800000
#define IN_DIM 128
#define EMB 64
#define HDIM 256
#define RR 12
#define BB 8
#define NGENE 20000
#define NPATH 2000
#define IN1 192
#define NR (NN * RR)

// ---------------- static scratch ----------------
__device__ float g_x0[(size_t)NN * IN1];
__device__ float g_h1[(size_t)NN * HDIM];
__device__ float g_h2[(size_t)NN * HDIM];
__device__ float g_aggB[(size_t)NN * BB * HDIM];
__device__ int   g_cnt[NR];          // zeroed at end of k_scan each run
__device__ int   g_off[NR + 1];
__device__ int   g_wof[NR];
__device__ int   g_esrc[EE];

// ---------------- helpers ----------------
__device__ __forceinline__ uint32_t pack2(float lo, float hi) {
    uint32_t r; asm("cvt.rn.bf16x2.f32 %0, %1, %2;" : "=r"(r) : "f"(hi), "f"(lo)); return r;
}
// word = bf16x2(lo half = a, hi half = b); residuals packed the same way
__device__ __forceinline__ void split_pair(float a, float b, uint32_t& wh, uint32_t& wl) {
    wh = pack2(a, b);
    float ra = __uint_as_float(wh << 16);
    float rb = __uint_as_float(wh & 0xFFFF0000u);
    wl = pack2(a - ra, b - rb);
}
__device__ __forceinline__ void mma16(float* d, const uint32_t* a, const uint32_t* b) {
    asm volatile(
        "mma.sync.aligned.m16n8k16.row.col.f32.bf16.bf16.f32 "
        "{%0,%1,%2,%3}, {%4,%5,%6,%7}, {%8,%9}, {%0,%1,%2,%3};"
        : "+f"(d[0]), "+f"(d[1]), "+f"(d[2]), "+f"(d[3])
        : "r"(a[0]), "r"(a[1]), "r"(a[2]), "r"(a[3]), "r"(b[0]), "r"(b[1]));
}

// ---------------- 1: build x0 + edge counts (g_cnt starts zeroed) ----------------
__global__ void k_build_count(const float* __restrict__ x,
                              const int* __restrict__ ei, const int* __restrict__ et) {
    int i = blockIdx.x * blockDim.x + threadIdx.x;
    if (i < EE) atomicAdd(&g_cnt[ei[EE + i] * RR + et[i]], 1);
    if (i >= NN * IN1) return;
    int n = i / IN1, c = i - n * IN1;
    g_x0[i] = (c < IN_DIM) ? x[(size_t)n * IN_DIM + c] : 0.0f;
}

// ---------------- 2: single-block scan; re-zero g_cnt for next run ----------------
__global__ void k_scan() {
    __shared__ int bs[1024];
    const int CH = (NR + 1023) / 1024;
    int t = threadIdx.x;
    int base = t * CH;
    int s = 0;
    for (int j = 0; j < CH; j++) {
        int i = base + j;
        if (i < NR) s += g_cnt[i];
    }
    bs[t] = s;
    __syncthreads();
    for (int off = 1; off < 1024; off <<= 1) {
        int v = (t >= off) ? bs[t - off] : 0;
        __syncthreads();
        bs[t] += v;
        __syncthreads();
    }
    int run = (t == 0) ? 0 : bs[t - 1];
    for (int j = 0; j < CH; j++) {
        int i = base + j;
        if (i < NR) {
            int c = g_cnt[i];
            g_off[i] = run;
            g_wof[i] = run;
            g_cnt[i] = 0;
            run += c;
        }
    }
    if (t == 1023) g_off[NR] = run;
}

// ---------------- 3: CSR fill + embedding adds ----------------
#define FILL_TOT (EE + (NGENE + NPATH) * EMB)
__global__ void k_fill_embs(const int* __restrict__ ei, const int* __restrict__ et,
                            const int* __restrict__ gidx, const int* __restrict__ pidx,
                            const float* __restrict__ gemb, const float* __restrict__ pemb) {
    int i = blockIdx.x * blockDim.x + threadIdx.x;
    if (i < EE) {
        int flat = ei[EE + i] * RR + et[i];
        int p = atomicAdd(&g_wof[flat], 1);
        g_esrc[p] = ei[i];
    } else if (i < EE + NGENE * EMB) {
        int t = i - EE;
        int g = t / EMB, j = t - g * EMB;
        g_x0[(size_t)gidx[g] * IN1 + IN_DIM + j] += gemb[t];
    } else if (i < FILL_TOT) {
        int t = i - EE - NGENE * EMB;
        int g = t / EMB, j = t - g * EMB;
        g_x0[(size_t)pidx[g] * IN1 + IN_DIM + j] += pemb[t];
    }
}

// ---------------- 4/6: gather-aggregate into aggB (uses g_off diffs) ----------------
template <int K, int LAYER>
__global__ void __launch_bounds__(K)
k_agg(const float* __restrict__ comp) {
    __shared__ float sc[RR * BB];
    const int tid = threadIdx.x;
    const int n = blockIdx.x;
    if (tid < RR * BB) sc[tid] = comp[tid];
    __syncthreads();

    const float* __restrict__ xin = (LAYER == 1) ? g_x0 : g_h1;

    float accB[BB];
#pragma unroll
    for (int b = 0; b < BB; b++) accB[b] = 0.f;

    int off0 = g_off[n * RR];
#pragma unroll
    for (int r = 0; r < RR; r++) {
        int off1 = g_off[n * RR + r + 1];
        int c = off1 - off0;
        if (c > 0) {
            float s = 0.f;
            for (int j = off0; j < off1; j++) {
                int src = __ldg(&g_esrc[j]);
                s += xin[(size_t)src * K + tid];
            }
            float smv = s / (float)c;
#pragma unroll
            for (int b = 0; b < BB; b++)
                accB[b] = fmaf(sc[r * BB + b], smv, accB[b]);
        }
        off0 = off1;
    }

    float* dst = g_aggB + (size_t)n * (BB * K) + tid;
#pragma unroll
    for (int b = 0; b < BB; b++) dst[b * K] = accB[b];
}

// ---------------- 5/7: GEMM 3xBF16 (m16n8k16) + bias + head-softmax ----------------
// CTA 128 rows x 256 cols, 8 warps (2x4), warp 64x64, BK=16, double-buffered pre-split smem.
// 32-bit word layout: A[2st][hi/lo][128][12] = 6144 | B[2st][hi/lo][8][264] = 8448 |
// bias@14592 att@14848 sc@15104(512) al@15616(512) -> 16128 words = 64512 B
#define GEMM_SMEM_BYTES (16128 * 4)

template <int KIN, int LAYER>
__global__ void __launch_bounds__(256, 1)
k_gemm(const float* __restrict__ basis, const float* __restrict__ root,
       const float* __restrict__ bias,  const float* __restrict__ att) {
    constexpr int KB   = BB * KIN;
    constexpr int KTOT = 9 * KIN;
    constexpr int T    = KTOT / 16;

    extern __shared__ float sm[];
    uint32_t* smw = reinterpret_cast<uint32_t*>(sm);
    float* s_bias = sm + 14592;
    float* s_att  = sm + 14848;
    float* s_sc   = sm + 15104;
    float* s_al   = sm + 15616;

    const int tid  = threadIdx.x;
    const int lane = tid & 31;
    const int wid  = tid >> 5;
    const int wm   = wid >> 2;
    const int wn   = wid & 3;
    const int m0   = blockIdx.x * 128;

    const float* xin  = (LAYER == 1) ? g_x0 : g_h1;
    float*       hout = (LAYER == 1) ? g_h1 : g_h2;

    s_bias[tid] = bias[tid];
    s_att[tid]  = att[tid];

    float acc[4][8][4];
#pragma unroll
    for (int a = 0; a < 4; a++)
#pragma unroll
        for (int b = 0; b < 8; b++)
#pragma unroll
            for (int c = 0; c < 4; c++) acc[a][b][c] = 0.f;

    float4 aReg[2];
    float4 bReg[2][2];

    auto gload = [&](int t) {
        int k0 = t * 16;
#pragma unroll
        for (int i = 0; i < 2; i++) {
            int id = tid + i * 256;
            int m = id >> 2, k4 = (id & 3) << 2;
            int row = m0 + m;
            int kc = k0 + k4;
            if (row < NN) {
                const float* src = (kc < KB) ? (g_aggB + (size_t)row * KB + kc)
                                             : (xin + (size_t)row * KIN + (kc - KB));
                aReg[i] = *reinterpret_cast<const float4*>(src);
            } else {
                aReg[i] = make_float4(0.f, 0.f, 0.f, 0.f);
            }
        }
#pragma unroll
        for (int i = 0; i < 2; i++) {
            int id = tid + i * 256;
            int kp = id >> 6, n4 = (id & 63) << 2;
            int kk = k0 + 2 * kp;   // kk,kk+1 never straddle the KB boundary (both even-pair)
            const float* s0, * s1;
            if (kk < KB) { s0 = basis + (size_t)kk * 256 + n4; s1 = s0 + 256; }
            else         { s0 = root + (size_t)(kk - KB) * 256 + n4; s1 = s0 + 256; }
            bReg[i][0] = *reinterpret_cast<const float4*>(s0);
            bReg[i][1] = *reinterpret_cast<const float4*>(s1);
        }
    };

    auto sstore = [&](int t) {
        int s = t & 1;
        uint32_t* Ah = smw + s * 3072;
        uint32_t* Al = Ah + 1536;
#pragma unroll
        for (int i = 0; i < 2; i++) {
            int id = tid + i * 256;
            int m = id >> 2, k4 = (id & 3) << 2;
            float4 v = aReg[i];
            uint32_t h0, l0, h1, l1;
            split_pair(v.x, v.y, h0, l0);
            split_pair(v.z, v.w, h1, l1);
            int w = m * 12 + (k4 >> 1);
            *reinterpret_cast<uint2*>(Ah + w) = make_uint2(h0, h1);
            *reinterpret_cast<uint2*>(Al + w) = make_uint2(l0, l1);
        }
        uint32_t* Bh = smw + 6144 + s * 4224;
        uint32_t* Bl = Bh + 2112;
#pragma unroll
        for (int i = 0; i < 2; i++) {
            int id = tid + i * 256;
            int kp = id >> 6, n4 = (id & 63) << 2;
            float4 va = bReg[i][0], vb = bReg[i][1];
            uint32_t h[4], l[4];
            split_pair(va.x, vb.x, h[0], l[0]);
            split_pair(va.y, vb.y, h[1], l[1]);
            split_pair(va.z, vb.z, h[2], l[2]);
            split_pair(va.w, vb.w, h[3], l[3]);
            int w = kp * 264 + n4;
            *reinterpret_cast<uint4*>(Bh + w) = make_uint4(h[0], h[1], h[2], h[3]);
            *reinterpret_cast<uint4*>(Bl + w) = make_uint4(l[0], l[1], l[2], l[3]);
        }
    };

    gload(0);
    sstore(0);
    if (T > 1) gload(1);
    __syncthreads();

    for (int t = 0; t < T; t++) {
        const uint32_t* Ah = smw + (t & 1) * 3072;
        const uint32_t* Bh = smw + 6144 + (t & 1) * 4224;
        const int c = lane & 3;

        uint32_t ah[4][4], al_[4][4];
#pragma unroll
        for (int mi = 0; mi < 4; mi++) {
            int r0 = wm * 64 + mi * 16 + (lane >> 2);
            int i0 = r0 * 12 + c;
            int i1 = (r0 + 8) * 12 + c;
            ah[mi][0] = Ah[i0];           ah[mi][1] = Ah[i1];
            ah[mi][2] = Ah[i0 + 4];       ah[mi][3] = Ah[i1 + 4];
            al_[mi][0] = Ah[1536 + i0];   al_[mi][1] = Ah[1536 + i1];
            al_[mi][2] = Ah[1536 + i0 + 4]; al_[mi][3] = Ah[1536 + i1 + 4];
        }
        uint32_t bh[8][2], bl[8][2];
#pragma unroll
        for (int ni = 0; ni < 8; ni++) {
            int n = wn * 64 + ni * 8 + (lane >> 2);
            bh[ni][0] = Bh[c * 264 + n];
            bh[ni][1] = Bh[(c + 4) * 264 + n];
            bl[ni][0] = Bh[2112 + c * 264 + n];
            bl[ni][1] = Bh[2112 + (c + 4) * 264 + n];
        }
        // term-major: accumulator reuse distance = 32 MMAs (no RAW stalls)
#pragma unroll
        for (int ni = 0; ni < 8; ni++)
#pragma unroll
            for (int mi = 0; mi < 4; mi++) mma16(acc[mi][ni], ah[mi], bh[ni]);
#pragma unroll
        for (int ni = 0; ni < 8; ni++)
#pragma unroll
            for (int mi = 0; mi < 4; mi++) mma16(acc[mi][ni], ah[mi], bl[ni]);
#pragma unroll
        for (int ni = 0; ni < 8; ni++)
#pragma unroll
            for (int mi = 0; mi < 4; mi++) mma16(acc[mi][ni], al_[mi], bh[ni]);

        if (t + 1 < T) sstore(t + 1);
        if (t + 2 < T) gload(t + 2);
        __syncthreads();
    }

    // ---- bias + head scores (warp tile == one full head) ----
    float sc[8];
#pragma unroll
    for (int i = 0; i < 8; ++i) sc[i] = 0.f;
#pragma unroll
    for (int mi = 0; mi < 4; ++mi)
#pragma unroll
        for (int ni = 0; ni < 8; ++ni) {
            int colb = wn * 64 + ni * 8 + (lane & 3) * 2;
#pragma unroll
            for (int r = 0; r < 4; ++r) {
                int col = colb + (r & 1);
                acc[mi][ni][r] += s_bias[col];
                sc[mi * 2 + (r >> 1)] = fmaf(acc[mi][ni][r], s_att[col], sc[mi * 2 + (r >> 1)]);
            }
        }
#pragma unroll
    for (int i = 0; i < 8; ++i) {
        sc[i] += __shfl_xor_sync(0xffffffffu, sc[i], 1);
        sc[i] += __shfl_xor_sync(0xffffffffu, sc[i], 2);
    }
    if ((lane & 3) == 0) {
#pragma unroll
        for (int mi = 0; mi < 4; ++mi) {
            int r0 = wm * 64 + mi * 16 + (lane >> 2);
            s_sc[r0 * 4 + wn]       = sc[mi * 2];
            s_sc[(r0 + 8) * 4 + wn] = sc[mi * 2 + 1];
        }
    }
    __syncthreads();
    if (tid < 128) {
        float v0 = s_sc[tid * 4], v1 = s_sc[tid * 4 + 1];
        float v2 = s_sc[tid * 4 + 2], v3 = s_sc[tid * 4 + 3];
        float mx = fmaxf(fmaxf(v0, v1), fmaxf(v2, v3));
        float e0 = expf(v0 - mx), e1 = expf(v1 - mx), e2 = expf(v2 - mx), e3 = expf(v3 - mx);
        float inv = 1.f / (e0 + e1 + e2 + e3);
        s_al[tid * 4]     = e0 * inv;
        s_al[tid * 4 + 1] = e1 * inv;
        s_al[tid * 4 + 2] = e2 * inv;
        s_al[tid * 4 + 3] = e3 * inv;
    }
    __syncthreads();

    // ---- scaled store ----
#pragma unroll
    for (int mi = 0; mi < 4; ++mi) {
        int lr0 = wm * 64 + mi * 16 + (lane >> 2);
        int rowA = m0 + lr0, rowB = rowA + 8;
        float aA = s_al[lr0 * 4 + wn];
        float aB = s_al[(lr0 + 8) * 4 + wn];
#pragma unroll
        for (int ni = 0; ni < 8; ++ni) {
            int col = wn * 64 + ni * 8 + (lane & 3) * 2;
            if (rowA < NN) {
                float2 o = make_float2(acc[mi][ni][0] * aA, acc[mi][ni][1] * aA);
                *reinterpret_cast<float2*>(&hout[(size_t)rowA * HDIM + col]) = o;
            }
            if (rowB < NN) {
                float2 o = make_float2(acc[mi][ni][2] * aB, acc[mi][ni][3] * aB);
                *reinterpret_cast<float2*>(&hout[(size_t)rowB * HDIM + col]) = o;
            }
        }
    }
}

// ---------------- 8: final prediction ----------------
__global__ void k_pred(const float* __restrict__ pw, const float* __restrict__ pb,
                       float* __restrict__ out) {
    __shared__ float wt[12 * HDIM];
    int tid = threadIdx.x;
    for (int i = tid; i < HDIM * 12; i += blockDim.x) {
        int c = i / 12, j = i - c * 12;
        wt[j * HDIM + c] = pw[i];
    }
    __syncthreads();
    int warp = tid >> 5, lane = tid & 31;
    int n = blockIdx.x * 8 + warp;
    if (n >= NN) return;
    float acc[12];
#pragma unroll
    for (int j = 0; j < 12; j++) acc[j] = 0.f;
#pragma unroll
    for (int c0 = 0; c0 < 8; c0++) {
        int c = c0 * 32 + lane;
        float v = g_h2[(size_t)n * HDIM + c];
#pragma unroll
        for (int j = 0; j < 12; j++) acc[j] = fmaf(v, wt[j * HDIM + c], acc[j]);
    }
#pragma unroll
    for (int j = 0; j < 12; j++) {
#pragma unroll
        for (int off = 16; off; off >>= 1)
            acc[j] += __shfl_xor_sync(0xffffffffu, acc[j], off);
    }
    if (lane == 0) {
#pragma unroll
        for (int j = 0; j < 12; j++) out[(size_t)n * 12 + j] = acc[j] + pb[j];
    }
}

// ---------------- launch ----------------
extern "C" void kernel_launch(void* const* d_in, const int* in_sizes, int n_in,
                              void* d_out, int out_size) {
    const float* x      = (const float*)d_in[0];
    const int*   ei     = (const int*)d_in[1];
    const int*   et     = (const int*)d_in[2];
    const int*   gidx   = (const int*)d_in[3];
    const int*   pidx   = (const int*)d_in[4];
    const float* gemb   = (const float*)d_in[5];
    const float* pemb   = (const float*)d_in[6];
    const float* comp1  = (const float*)d_in[7];
    const float* basis1 = (const float*)d_in[8];
    const float* root1  = (const float*)d_in[9];
    const float* bias1  = (const float*)d_in[10];
    const float* att1   = (const float*)d_in[11];
    const float* comp2  = (const float*)d_in[12];
    const float* basis2 = (const float*)d_in[13];
    const float* root2  = (const float*)d_in[14];
    const float* bias2  = (const float*)d_in[15];
    const float* att2   = (const float*)d_in[16];
    const float* predw  = (const float*)d_in[17];
    const float* predb  = (const float*)d_in[18];
    float* out = (float*)d_out;

    const int TPB = 256;

    cudaFuncSetAttribute(k_gemm<IN1, 1>,  cudaFuncAttributeMaxDynamicSharedMemorySize, GEMM_SMEM_BYTES);
    cudaFuncSetAttribute(k_gemm<HDIM, 2>, cudaFuncAttributeMaxDynamicSharedMemorySize, GEMM_SMEM_BYTES);

    // 1: x0 + counts (g_cnt zeroed by previous k_scan / static init)
    k_build_count<<<(NN * IN1 + TPB - 1) / TPB, TPB>>>(x, ei, et);
    // 2: scan -> offsets (+ re-zero g_cnt)
    k_scan<<<1, 1024>>>();
    // 3: CSR fill + embeddings
    k_fill_embs<<<(FILL_TOT + TPB - 1) / TPB, TPB>>>(ei, et, gidx, pidx, gemb, pemb);
    // 4: aggregate layer 1 (profiled slot)
    k_agg<IN1, 1><<<NN, IN1>>>(comp1);
    // 5: GEMM layer 1
    k_gemm<IN1, 1><<<(NN + 127) / 128, 256, GEMM_SMEM_BYTES>>>(basis1, root1, bias1, att1);
    // 6: aggregate layer 2
    k_agg<HDIM, 2><<<NN, HDIM>>>(comp2);
    // 7: GEMM layer 2
    k_gemm<HDIM, 2><<<(NN + 127) / 128, 256, GEMM_SMEM_BYTES>>>(basis2, root2, bias2, att2);
    // 8: prediction head
    k_pred<<<(NN + 7) / 8, TPB>>>(predw, predb, out);
}

// round 7
// speedup vs baseline: 1.5255x; 1.2185x over previous
#include <cuda_runtime.h>
#include <cuda_fp16.h>
#include <math.h>
#include <stdint.h>

#define NN 50000
#define EE 800000
#define IN_DIM 128
#define EMB 64
#define HDIM 256
#define RR 12
#define BB 8
#define NGENE 20000
#define NPATH 2000
#define IN1 192
#define NR (NN * RR)

// ---------------- static scratch ----------------
__device__ float g_x0[(size_t)NN * IN1];
__device__ float g_h1[(size_t)NN * HDIM];
__device__ float g_h2[(size_t)NN * HDIM];
__device__ float g_aggB[(size_t)NN * BB * HDIM];
__device__ int   g_cnt[NR];          // zeroed at end of k_scan each run
__device__ int   g_off[NR + 1];
__device__ int   g_wof[NR];
__device__ int   g_esrc[EE];

// ---------------- helpers ----------------
__device__ __forceinline__ uint32_t packh2(float a, float b) {   // low=a, high=b
    half2 h = __floats2half2_rn(a, b);
    return *reinterpret_cast<uint32_t*>(&h);
}
__device__ __forceinline__ void split_pair_h(float a, float b, uint32_t& wh, uint32_t& wl) {
    half2 h = __floats2half2_rn(a, b);
    float2 r = __half22float2(h);
    half2 l = __floats2half2_rn(a - r.x, b - r.y);
    wh = *reinterpret_cast<uint32_t*>(&h);
    wl = *reinterpret_cast<uint32_t*>(&l);
}
__device__ __forceinline__ void mma16h(float* d, const uint32_t* a, const uint32_t* b) {
    asm volatile(
        "mma.sync.aligned.m16n8k16.row.col.f32.f16.f16.f32 "
        "{%0,%1,%2,%3}, {%4,%5,%6,%7}, {%8,%9}, {%0,%1,%2,%3};"
        : "+f"(d[0]), "+f"(d[1]), "+f"(d[2]), "+f"(d[3])
        : "r"(a[0]), "r"(a[1]), "r"(a[2]), "r"(a[3]), "r"(b[0]), "r"(b[1]));
}
#define BSCALE 256.0f
#define INV_BSCALE (1.0f / 256.0f)

// ---------------- 1: build x0 + edge counts (g_cnt starts zeroed) ----------------
__global__ void k_build_count(const float* __restrict__ x,
                              const int* __restrict__ ei, const int* __restrict__ et) {
    int i = blockIdx.x * blockDim.x + threadIdx.x;
    if (i < EE) atomicAdd(&g_cnt[ei[EE + i] * RR + et[i]], 1);
    if (i >= NN * IN1) return;
    int n = i / IN1, c = i - n * IN1;
    g_x0[i] = (c < IN_DIM) ? x[(size_t)n * IN_DIM + c] : 0.0f;
}

// ---------------- 2: single-block scan; re-zero g_cnt for next run ----------------
__global__ void k_scan() {
    __shared__ int bs[1024];
    const int CH = (NR + 1023) / 1024;
    int t = threadIdx.x;
    int base = t * CH;
    int s = 0;
    for (int j = 0; j < CH; j++) {
        int i = base + j;
        if (i < NR) s += g_cnt[i];
    }
    bs[t] = s;
    __syncthreads();
    for (int off = 1; off < 1024; off <<= 1) {
        int v = (t >= off) ? bs[t - off] : 0;
        __syncthreads();
        bs[t] += v;
        __syncthreads();
    }
    int run = (t == 0) ? 0 : bs[t - 1];
    for (int j = 0; j < CH; j++) {
        int i = base + j;
        if (i < NR) {
            int c = g_cnt[i];
            g_off[i] = run;
            g_wof[i] = run;
            g_cnt[i] = 0;
            run += c;
        }
    }
    if (t == 1023) g_off[NR] = run;
}

// ---------------- 3: CSR fill + embedding adds ----------------
#define FILL_TOT (EE + (NGENE + NPATH) * EMB)
__global__ void k_fill_embs(const int* __restrict__ ei, const int* __restrict__ et,
                            const int* __restrict__ gidx, const int* __restrict__ pidx,
                            const float* __restrict__ gemb, const float* __restrict__ pemb) {
    int i = blockIdx.x * blockDim.x + threadIdx.x;
    if (i < EE) {
        int flat = ei[EE + i] * RR + et[i];
        int p = atomicAdd(&g_wof[flat], 1);
        g_esrc[p] = ei[i];
    } else if (i < EE + NGENE * EMB) {
        int t = i - EE;
        int g = t / EMB, j = t - g * EMB;
        g_x0[(size_t)gidx[g] * IN1 + IN_DIM + j] += gemb[t];
    } else if (i < FILL_TOT) {
        int t = i - EE - NGENE * EMB;
        int g = t / EMB, j = t - g * EMB;
        g_x0[(size_t)pidx[g] * IN1 + IN_DIM + j] += pemb[t];
    }
}

// ---------------- 4/6: gather-aggregate into aggB, float4 per thread ----------------
template <int K, int LAYER>
__global__ void __launch_bounds__(K / 4)
k_agg(const float* __restrict__ comp) {
    __shared__ float sc[RR * BB];
    const int tid = threadIdx.x;          // 0 .. K/4-1
    const int n = blockIdx.x;
    for (int i = tid; i < RR * BB; i += K / 4) sc[i] = comp[i];
    __syncthreads();

    const float* __restrict__ xin = (LAYER == 1) ? g_x0 : g_h1;
    const int col = tid * 4;

    float4 accB[BB];
#pragma unroll
    for (int b = 0; b < BB; b++) accB[b] = make_float4(0.f, 0.f, 0.f, 0.f);

    int off0 = g_off[n * RR];
#pragma unroll
    for (int r = 0; r < RR; r++) {
        int off1 = g_off[n * RR + r + 1];
        int c = off1 - off0;
        if (c > 0) {
            float4 s = make_float4(0.f, 0.f, 0.f, 0.f);
            for (int j = off0; j < off1; j++) {
                int src = __ldg(&g_esrc[j]);
                float4 v = *reinterpret_cast<const float4*>(xin + (size_t)src * K + col);
                s.x += v.x; s.y += v.y; s.z += v.z; s.w += v.w;
            }
            float inv = 1.f / (float)c;
            float4 sm = make_float4(s.x * inv, s.y * inv, s.z * inv, s.w * inv);
#pragma unroll
            for (int b = 0; b < BB; b++) {
                float w = sc[r * BB + b];
                accB[b].x = fmaf(w, sm.x, accB[b].x);
                accB[b].y = fmaf(w, sm.y, accB[b].y);
                accB[b].z = fmaf(w, sm.z, accB[b].z);
                accB[b].w = fmaf(w, sm.w, accB[b].w);
            }
        }
        off0 = off1;
    }

    float* dst = g_aggB + (size_t)n * (BB * K) + col;
#pragma unroll
    for (int b = 0; b < BB; b++)
        *reinterpret_cast<float4*>(dst + b * K) = accB[b];
}

// ---------------- 5/7: GEMM 2-term FP16 (m16n8k16) + bias + head-softmax ----------------
// CTA 128 rows x 256 cols, 8 warps (2x4), warp 64x64, BK=16, double-buffered pre-split smem.
// word layout: A[2st][128][12] = 3072 | B[2st][hi/lo][8][264] = 8448 (@3072) |
// bias@11520 att@11776 sc@12032(512) al@12544(512) -> 13056 words = 52224 B
#define GEMM_SMEM_BYTES (13056 * 4)

template <int KIN, int LAYER>
__global__ void __launch_bounds__(256, 1)
k_gemm(const float* __restrict__ basis, const float* __restrict__ root,
       const float* __restrict__ bias,  const float* __restrict__ att) {
    constexpr int KB   = BB * KIN;
    constexpr int KTOT = 9 * KIN;
    constexpr int T    = KTOT / 16;

    extern __shared__ float sm[];
    uint32_t* smw = reinterpret_cast<uint32_t*>(sm);
    float* s_bias = sm + 11520;
    float* s_att  = sm + 11776;
    float* s_sc   = sm + 12032;
    float* s_al   = sm + 12544;

    const int tid  = threadIdx.x;
    const int lane = tid & 31;
    const int wid  = tid >> 5;
    const int wm   = wid >> 2;
    const int wn   = wid & 3;
    const int m0   = blockIdx.x * 128;

    const float* xin  = (LAYER == 1) ? g_x0 : g_h1;
    float*       hout = (LAYER == 1) ? g_h1 : g_h2;

    s_bias[tid] = bias[tid];
    s_att[tid]  = att[tid];

    float acc[4][8][4];
#pragma unroll
    for (int a = 0; a < 4; a++)
#pragma unroll
        for (int b = 0; b < 8; b++)
#pragma unroll
            for (int c = 0; c < 4; c++) acc[a][b][c] = 0.f;

    float4 aReg[2];
    float4 bReg[2][2];

    auto gload = [&](int t) {
        int k0 = t * 16;
#pragma unroll
        for (int i = 0; i < 2; i++) {
            int id = tid + i * 256;
            int m = id >> 2, k4 = (id & 3) << 2;
            int row = m0 + m;
            int kc = k0 + k4;
            if (row < NN) {
                const float* src = (kc < KB) ? (g_aggB + (size_t)row * KB + kc)
                                             : (xin + (size_t)row * KIN + (kc - KB));
                aReg[i] = *reinterpret_cast<const float4*>(src);
            } else {
                aReg[i] = make_float4(0.f, 0.f, 0.f, 0.f);
            }
        }
#pragma unroll
        for (int i = 0; i < 2; i++) {
            int id = tid + i * 256;
            int kp = id >> 6, n4 = (id & 63) << 2;
            int kk = k0 + 2 * kp;
            const float* s0, * s1;
            if (kk < KB) { s0 = basis + (size_t)kk * 256 + n4; s1 = s0 + 256; }
            else         { s0 = root + (size_t)(kk - KB) * 256 + n4; s1 = s0 + 256; }
            bReg[i][0] = *reinterpret_cast<const float4*>(s0);
            bReg[i][1] = *reinterpret_cast<const float4*>(s1);
        }
    };

    auto sstore = [&](int t) {
        int s = t & 1;
        uint32_t* Ah = smw + s * 1536;
#pragma unroll
        for (int i = 0; i < 2; i++) {
            int id = tid + i * 256;
            int m = id >> 2, k4 = (id & 3) << 2;
            float4 v = aReg[i];
            uint32_t h0 = packh2(v.x, v.y);
            uint32_t h1 = packh2(v.z, v.w);
            int w = m * 12 + (k4 >> 1);
            *reinterpret_cast<uint2*>(Ah + w) = make_uint2(h0, h1);
        }
        uint32_t* Bh = smw + 3072 + s * 4224;
        uint32_t* Bl = Bh + 2112;
#pragma unroll
        for (int i = 0; i < 2; i++) {
            int id = tid + i * 256;
            int kp = id >> 6, n4 = (id & 63) << 2;
            float4 va = bReg[i][0], vb = bReg[i][1];
            uint32_t h[4], l[4];
            split_pair_h(va.x * BSCALE, vb.x * BSCALE, h[0], l[0]);
            split_pair_h(va.y * BSCALE, vb.y * BSCALE, h[1], l[1]);
            split_pair_h(va.z * BSCALE, vb.z * BSCALE, h[2], l[2]);
            split_pair_h(va.w * BSCALE, vb.w * BSCALE, h[3], l[3]);
            int w = kp * 264 + n4;
            *reinterpret_cast<uint4*>(Bh + w) = make_uint4(h[0], h[1], h[2], h[3]);
            *reinterpret_cast<uint4*>(Bl + w) = make_uint4(l[0], l[1], l[2], l[3]);
        }
    };

    gload(0);
    sstore(0);
    if (T > 1) gload(1);
    __syncthreads();

    for (int t = 0; t < T; t++) {
        const uint32_t* Ah = smw + (t & 1) * 1536;
        const uint32_t* Bh = smw + 3072 + (t & 1) * 4224;
        const int c = lane & 3;

        uint32_t ah[4][4];
#pragma unroll
        for (int mi = 0; mi < 4; mi++) {
            int r0 = wm * 64 + mi * 16 + (lane >> 2);
            int i0 = r0 * 12 + c;
            int i1 = (r0 + 8) * 12 + c;
            ah[mi][0] = Ah[i0];     ah[mi][1] = Ah[i1];
            ah[mi][2] = Ah[i0 + 4]; ah[mi][3] = Ah[i1 + 4];
        }
        uint32_t bh[8][2], bl[8][2];
#pragma unroll
        for (int ni = 0; ni < 8; ni++) {
            int n = wn * 64 + ni * 8 + (lane >> 2);
            bh[ni][0] = Bh[c * 264 + n];
            bh[ni][1] = Bh[(c + 4) * 264 + n];
            bl[ni][0] = Bh[2112 + c * 264 + n];
            bl[ni][1] = Bh[2112 + (c + 4) * 264 + n];
        }
        // term-major: accumulator reuse distance = 32 MMAs
#pragma unroll
        for (int ni = 0; ni < 8; ni++)
#pragma unroll
            for (int mi = 0; mi < 4; mi++) mma16h(acc[mi][ni], ah[mi], bh[ni]);
#pragma unroll
        for (int ni = 0; ni < 8; ni++)
#pragma unroll
            for (int mi = 0; mi < 4; mi++) mma16h(acc[mi][ni], ah[mi], bl[ni]);

        if (t + 1 < T) sstore(t + 1);
        if (t + 2 < T) gload(t + 2);
        __syncthreads();
    }

    // ---- unscale + bias + head scores (warp tile == one full head) ----
    float sc[8];
#pragma unroll
    for (int i = 0; i < 8; ++i) sc[i] = 0.f;
#pragma unroll
    for (int mi = 0; mi < 4; ++mi)
#pragma unroll
        for (int ni = 0; ni < 8; ++ni) {
            int colb = wn * 64 + ni * 8 + (lane & 3) * 2;
#pragma unroll
            for (int r = 0; r < 4; ++r) {
                int col = colb + (r & 1);
                acc[mi][ni][r] = fmaf(acc[mi][ni][r], INV_BSCALE, s_bias[col]);
                sc[mi * 2 + (r >> 1)] = fmaf(acc[mi][ni][r], s_att[col], sc[mi * 2 + (r >> 1)]);
            }
        }
#pragma unroll
    for (int i = 0; i < 8; ++i) {
        sc[i] += __shfl_xor_sync(0xffffffffu, sc[i], 1);
        sc[i] += __shfl_xor_sync(0xffffffffu, sc[i], 2);
    }
    if ((lane & 3) == 0) {
#pragma unroll
        for (int mi = 0; mi < 4; ++mi) {
            int r0 = wm * 64 + mi * 16 + (lane >> 2);
            s_sc[r0 * 4 + wn]       = sc[mi * 2];
            s_sc[(r0 + 8) * 4 + wn] = sc[mi * 2 + 1];
        }
    }
    __syncthreads();
    if (tid < 128) {
        float v0 = s_sc[tid * 4], v1 = s_sc[tid * 4 + 1];
        float v2 = s_sc[tid * 4 + 2], v3 = s_sc[tid * 4 + 3];
        float mx = fmaxf(fmaxf(v0, v1), fmaxf(v2, v3));
        float e0 = expf(v0 - mx), e1 = expf(v1 - mx), e2 = expf(v2 - mx), e3 = expf(v3 - mx);
        float inv = 1.f / (e0 + e1 + e2 + e3);
        s_al[tid * 4]     = e0 * inv;
        s_al[tid * 4 + 1] = e1 * inv;
        s_al[tid * 4 + 2] = e2 * inv;
        s_al[tid * 4 + 3] = e3 * inv;
    }
    __syncthreads();

    // ---- scaled store ----
#pragma unroll
    for (int mi = 0; mi < 4; ++mi) {
        int lr0 = wm * 64 + mi * 16 + (lane >> 2);
        int rowA = m0 + lr0, rowB = rowA + 8;
        float aA = s_al[lr0 * 4 + wn];
        float aB = s_al[(lr0 + 8) * 4 + wn];
#pragma unroll
        for (int ni = 0; ni < 8; ++ni) {
            int col = wn * 64 + ni * 8 + (lane & 3) * 2;
            if (rowA < NN) {
                float2 o = make_float2(acc[mi][ni][0] * aA, acc[mi][ni][1] * aA);
                *reinterpret_cast<float2*>(&hout[(size_t)rowA * HDIM + col]) = o;
            }
            if (rowB < NN) {
                float2 o = make_float2(acc[mi][ni][2] * aB, acc[mi][ni][3] * aB);
                *reinterpret_cast<float2*>(&hout[(size_t)rowB * HDIM + col]) = o;
            }
        }
    }
}

// ---------------- 8: final prediction ----------------
__global__ void k_pred(const float* __restrict__ pw, const float* __restrict__ pb,
                       float* __restrict__ out) {
    __shared__ float wt[12 * HDIM];
    int tid = threadIdx.x;
    for (int i = tid; i < HDIM * 12; i += blockDim.x) {
        int c = i / 12, j = i - c * 12;
        wt[j * HDIM + c] = pw[i];
    }
    __syncthreads();
    int warp = tid >> 5, lane = tid & 31;
    int n = blockIdx.x * 8 + warp;
    if (n >= NN) return;
    float acc[12];
#pragma unroll
    for (int j = 0; j < 12; j++) acc[j] = 0.f;
#pragma unroll
    for (int c0 = 0; c0 < 8; c0++) {
        int c = c0 * 32 + lane;
        float v = g_h2[(size_t)n * HDIM + c];
#pragma unroll
        for (int j = 0; j < 12; j++) acc[j] = fmaf(v, wt[j * HDIM + c], acc[j]);
    }
#pragma unroll
    for (int j = 0; j < 12; j++) {
#pragma unroll
        for (int off = 16; off; off >>= 1)
            acc[j] += __shfl_xor_sync(0xffffffffu, acc[j], off);
    }
    if (lane == 0) {
#pragma unroll
        for (int j = 0; j < 12; j++) out[(size_t)n * 12 + j] = acc[j] + pb[j];
    }
}

// ---------------- launch ----------------
extern "C" void kernel_launch(void* const* d_in, const int* in_sizes, int n_in,
                              void* d_out, int out_size) {
    const float* x      = (const float*)d_in[0];
    const int*   ei     = (const int*)d_in[1];
    const int*   et     = (const int*)d_in[2];
    const int*   gidx   = (const int*)d_in[3];
    const int*   pidx   = (const int*)d_in[4];
    const float* gemb   = (const float*)d_in[5];
    const float* pemb   = (const float*)d_in[6];
    const float* comp1  = (const float*)d_in[7];
    const float* basis1 = (const float*)d_in[8];
    const float* root1  = (const float*)d_in[9];
    const float* bias1  = (const float*)d_in[10];
    const float* att1   = (const float*)d_in[11];
    const float* comp2  = (const float*)d_in[12];
    const float* basis2 = (const float*)d_in[13];
    const float* root2  = (const float*)d_in[14];
    const float* bias2  = (const float*)d_in[15];
    const float* att2   = (const float*)d_in[16];
    const float* predw  = (const float*)d_in[17];
    const float* predb  = (const float*)d_in[18];
    float* out = (float*)d_out;

    const int TPB = 256;

    cudaFuncSetAttribute(k_gemm<IN1, 1>,  cudaFuncAttributeMaxDynamicSharedMemorySize, GEMM_SMEM_BYTES);
    cudaFuncSetAttribute(k_gemm<HDIM, 2>, cudaFuncAttributeMaxDynamicSharedMemorySize, GEMM_SMEM_BYTES);

    // 1: x0 + counts (g_cnt zeroed by previous k_scan / static init)
    k_build_count<<<(NN * IN1 + TPB - 1) / TPB, TPB>>>(x, ei, et);
    // 2: scan -> offsets (+ re-zero g_cnt)
    k_scan<<<1, 1024>>>();
    // 3: CSR fill + embeddings
    k_fill_embs<<<(FILL_TOT + TPB - 1) / TPB, TPB>>>(ei, et, gidx, pidx, gemb, pemb);
    // 4: aggregate layer 1 (profiled slot)
    k_agg<IN1, 1><<<NN, IN1 / 4>>>(comp1);
    // 5: GEMM layer 1
    k_gemm<IN1, 1><<<(NN + 127) / 128, 256, GEMM_SMEM_BYTES>>>(basis1, root1, bias1, att1);
    // 6: aggregate layer 2
    k_agg<HDIM, 2><<<NN, HDIM / 4>>>(comp2);
    // 7: GEMM layer 2
    k_gemm<HDIM, 2><<<(NN + 127) / 128, 256, GEMM_SMEM_BYTES>>>(basis2, root2, bias2, att2);
    // 8: prediction head
    k_pred<<<(NN + 7) / 8, TPB>>>(predw, predb, out);
}